// round 16
// baseline (speedup 1.0000x reference)
#include <cuda_runtime.h>
#include <cuda_fp16.h>
#include <cstdint>

#define SEQ   4096
#define DIM   512
#define VOCAB 32000
#define NBLK  4

#define NCHUNK 128
#define CHUNK  (SEQ / NCHUNK)   // 32

// ---------------- scratch (no allocations allowed) ----------------
__device__ float   g_x [SEQ * DIM];
__device__ __half  g_xn[SEQ * DIM];                 // fp16 rmsnorm output (GEMM A)
__device__ __half2 g_cw[SEQ * DIM];                 // packed (c, w) per element
__device__ float2  g_CsWs[NCHUNK * DIM];            // packed per-chunk (C, W) summaries
__device__ __half  g_roT [VOCAB * DIM];             // readout^T  [32000, 512] fp16
__device__ __half  g_whgT[NBLK * 2 * DIM * DIM];    // w_hg^T, column-interleaved, fp16

// ---------------- helpers ----------------
__device__ __forceinline__ uint32_t smem_u32(const void* p) {
    return (uint32_t)__cvta_generic_to_shared(p);
}
__device__ __forceinline__ void cp_async16(uint32_t saddr, const void* gmem) {
    asm volatile("cp.async.cg.shared.global [%0], [%1], 16;\n" :: "r"(saddr), "l"(gmem));
}
#define CP_COMMIT() asm volatile("cp.async.commit_group;\n" ::: "memory")
#define CP_WAIT1()  asm volatile("cp.async.wait_group 1;\n" ::: "memory")
#define CP_WAIT0()  asm volatile("cp.async.wait_group 0;\n" ::: "memory")

#define LDSM4(r, addr) \
    asm volatile("ldmatrix.sync.aligned.m8n8.x4.shared.b16 {%0,%1,%2,%3}, [%4];" \
        : "=r"((r)[0]), "=r"((r)[1]), "=r"((r)[2]), "=r"((r)[3]) : "r"(addr))

__device__ __forceinline__ void mma_f16(float* c, const uint32_t* a,
                                        uint32_t b0, uint32_t b1) {
    asm volatile(
        "mma.sync.aligned.m16n8k16.row.col.f32.f16.f16.f32 "
        "{%0,%1,%2,%3}, {%4,%5,%6,%7}, {%8,%9}, {%0,%1,%2,%3};"
        : "+f"(c[0]), "+f"(c[1]), "+f"(c[2]), "+f"(c[3])
        : "r"(a[0]), "r"(a[1]), "r"(a[2]), "r"(a[3]), "r"(b0), "r"(b1));
}

// streaming (evict-first) store: output logits are never reread -> keep B in L2
__device__ __forceinline__ void stg_cs_f2(float* p, float a, float b) {
    asm volatile("st.global.cs.v2.f32 [%0], {%1, %2};" :: "l"(p), "f"(a), "f"(b) : "memory");
}

// ---------------- elementwise / prep kernels ----------------

// readout: src [K, N] f32 -> dst [N, K] fp16
__global__ void transpose_h(const float* __restrict__ src, __half* __restrict__ dst,
                            int K, int N) {
    __shared__ float t[32][33];
    int n0 = blockIdx.x * 32, k0 = blockIdx.y * 32;
    int tx = threadIdx.x, ty = threadIdx.y;                 // 32 x 8
    #pragma unroll
    for (int i = 0; i < 32; i += 8)
        t[ty + i][tx] = src[(size_t)(k0 + ty + i) * N + n0 + tx];
    __syncthreads();
    #pragma unroll
    for (int i = 0; i < 32; i += 8)
        dst[(size_t)(n0 + ty + i) * K + k0 + tx] = __float2half_rn(t[tx][ty + i]);
}

// w_hg: src [K, 2D] f32 -> dst [2D, K] fp16, column-interleaved:
//   hidden ch n -> row 2n, gate ch n -> row 2n+1
__global__ void transpose_h_ilv(const float* __restrict__ src0, __half* __restrict__ dst0,
                                int K, int N) {
    const float* src = src0 + (size_t)blockIdx.z * K * N;
    __half* dst = dst0 + (size_t)blockIdx.z * N * K;
    __shared__ float t[32][33];
    int n0 = blockIdx.x * 32, k0 = blockIdx.y * 32;
    int tx = threadIdx.x, ty = threadIdx.y;
    #pragma unroll
    for (int i = 0; i < 32; i += 8)
        t[ty + i][tx] = src[(size_t)(k0 + ty + i) * N + n0 + tx];
    __syncthreads();
    #pragma unroll
    for (int i = 0; i < 32; i += 8) {
        int n = n0 + ty + i;
        int np = (n < DIM) ? (2 * n) : (2 * (n - DIM) + 1);
        dst[(size_t)np * K + k0 + tx] = __float2half_rn(t[tx][ty + i]);
    }
}

// fused embed gather + rmsnorm: x = emb[ids], xn = rmsnorm(x)*scale (fp16)
__global__ void embed_norm(const int* __restrict__ ids,
                           const float* __restrict__ emb,
                           const float* __restrict__ scale,
                           float* __restrict__ x, __half* __restrict__ xn) {
    int t = blockIdx.x;
    int tid = threadIdx.x;                                // 128 threads, 4 f32 each
    float4 v = ((const float4*)(emb + (size_t)ids[t] * DIM))[tid];
    ((float4*)(x + (size_t)t * DIM))[tid] = v;
    float ss = v.x * v.x + v.y * v.y + v.z * v.z + v.w * v.w;
    #pragma unroll
    for (int o = 16; o; o >>= 1) ss += __shfl_xor_sync(0xffffffffu, ss, o);
    __shared__ float sred[4];
    if ((tid & 31) == 0) sred[tid >> 5] = ss;
    __syncthreads();
    ss = sred[0] + sred[1] + sred[2] + sred[3];
    float r = rsqrtf(ss * (1.0f / DIM) + 1e-6f);
    float4 s = ((const float4*)scale)[tid];
    __half2 h0 = __floats2half2_rn(v.x * r * s.x, v.y * r * s.y);
    __half2 h1 = __floats2half2_rn(v.z * r * s.z, v.w * r * s.w);
    ((__half2*)(xn + (size_t)t * DIM))[2 * tid]     = h0;
    ((__half2*)(xn + (size_t)t * DIM))[2 * tid + 1] = h1;
}

// ---------------- scan kernel ----------------
// fused: per-block carry from packed chunk summaries, apply scan + residual,
// stage tile in smem (ONE barrier), then per-timestep rmsnorm -> fp16 xn.
// LAST: skip the (dead) x writeback on the final layer.
// 512 threads, 64 KB dynamic smem.  c,w consumed as packed fp16.
template<bool LAST>
__global__ void scan3_norm3(const __half2* __restrict__ cw,
                            const float2* __restrict__ CsWs,
                            const float* __restrict__ scale,
                            float* __restrict__ x, __half* __restrict__ xn) {
    extern __shared__ float sx[];                         // [CHUNK][DIM]
    int d = threadIdx.x;                                  // 512
    int b = blockIdx.x;

    // carry: prefix of chunk summaries 0..b-1 (fp32-accurate)
    float h = 0.0f;
    for (int j = 0; j < b; j++) {
        float2 s = CsWs[j * DIM + d];
        h = fmaf(s.x, h, s.y);
    }

    size_t base = (size_t)b * CHUNK * DIM + d;
    #pragma unroll 4
    for (int j = 0; j < CHUNK; j++) {
        size_t p = base + (size_t)j * DIM;
        float2 v2 = __half22float2(cw[p]);
        h = fmaf(v2.x, h, v2.y);
        float xv = x[p] + h;
        if (!LAST) x[p] = xv;
        sx[j * DIM + d] = xv;
    }
    __syncthreads();

    int lane = d & 31, wid = d >> 5;                      // 16 warps
    #pragma unroll
    for (int ts = wid; ts < CHUNK; ts += 16) {
        const float4* row = (const float4*)(sx + ts * DIM);
        float4 v[4];
        float ss = 0.0f;
        #pragma unroll
        for (int i = 0; i < 4; i++) {
            v[i] = row[lane * 4 + i];
            ss += v[i].x * v[i].x + v[i].y * v[i].y + v[i].z * v[i].z + v[i].w * v[i].w;
        }
        #pragma unroll
        for (int o = 16; o; o >>= 1) ss += __shfl_xor_sync(0xffffffffu, ss, o);
        float r = rsqrtf(ss * (1.0f / DIM) + 1e-6f);
        __half2* dst = (__half2*)(xn + ((size_t)(b * CHUNK + ts)) * DIM + lane * 16);
        #pragma unroll
        for (int i = 0; i < 4; i++) {
            float4 s = ((const float4*)scale)[lane * 4 + i];
            dst[2 * i]     = __floats2half2_rn(v[i].x * r * s.x, v[i].y * r * s.y);
            dst[2 * i + 1] = __floats2half2_rn(v[i].z * r * s.z, v[i].w * r * s.w);
        }
    }
}

// ---------------- readout GEMM (unchanged winner) ----------------
// CTA 128x128, 256 threads, warp tile 64x32 (2x4 warps), BK=64,
// 3-stage cp.async (96 KB) -> 2 CTAs/SM.  f32 C via streaming stores.

#define GK  512
#define GBK 64
#define NKT (GK / GBK)                     // 8
#define BM  128
#define BN  128
#define GSTAGES 3
#define A_BYTES (BM * 128)                 // 16 KB
#define B_BYTES (BN * 128)                 // 16 KB
#define STAGE_BYTES (A_BYTES + B_BYTES)    // 32 KB
#define GEMM_SMEM (GSTAGES * STAGE_BYTES)  // 96 KB

__device__ __forceinline__ void load_stage_g(uint32_t sbase, int stage,
                                             const __half* Ab, const __half* Bb,
                                             int kt, int tid) {
    uint32_t sa = sbase + stage * STAGE_BYTES;
    int j = tid & 7;
    int rt = tid >> 3;                     // 0..31
    const __half* Ag = Ab + kt * GBK + j * 8;
    #pragma unroll
    for (int i = 0; i < 4; i++) {
        int r = i * 32 + rt;
        cp_async16(sa + r * 128 + ((j ^ (r & 7)) << 4), Ag + (size_t)r * GK);
    }
    uint32_t sb = sa + A_BYTES;
    const __half* Bg = Bb + kt * GBK + j * 8;
    #pragma unroll
    for (int i = 0; i < 4; i++) {
        int r = i * 32 + rt;
        cp_async16(sb + r * 128 + ((j ^ (r & 7)) << 4), Bg + (size_t)r * GK);
    }
}

__global__ __launch_bounds__(256, 2)
void gemm_ro(const __half* __restrict__ A, const __half* __restrict__ BT,
             float* __restrict__ C, int N) {
    extern __shared__ char smc[];
    uint32_t sbase = smem_u32(smc);

    int tid  = threadIdx.x;
    int lane = tid & 31;
    int wid  = tid >> 5;
    int wm = wid & 1;
    int wn = wid >> 1;
    int bm = blockIdx.x, bn = blockIdx.y;

    const __half* Ab = A  + (size_t)bm * BM * GK;
    const __half* Bb = BT + (size_t)bn * BN * GK;

    float acc[4][4][4];
    #pragma unroll
    for (int mf = 0; mf < 4; mf++)
        #pragma unroll
        for (int nf = 0; nf < 4; nf++)
            #pragma unroll
            for (int i = 0; i < 4; i++) acc[mf][nf][i] = 0.0f;

    int arow_l = (lane & 7) + ((lane >> 3) & 1) * 8;
    int adj    = (lane >> 4) & 1;
    int brow_l = (lane & 7) + ((lane >> 4) & 1) * 8;
    int bdj    = (lane >> 3) & 1;

    #pragma unroll
    for (int s = 0; s < GSTAGES - 1; s++) {
        load_stage_g(sbase, s, Ab, Bb, s, tid);
        CP_COMMIT();
    }

    for (int kt = 0; kt < NKT; kt++) {
        CP_WAIT1();
        __syncthreads();

        if (kt + GSTAGES - 1 < NKT)
            load_stage_g(sbase, (kt + GSTAGES - 1) % GSTAGES, Ab, Bb,
                         kt + GSTAGES - 1, tid);
        CP_COMMIT();

        uint32_t sa = sbase + (kt % GSTAGES) * STAGE_BYTES;
        uint32_t sb = sa + A_BYTES;

        #pragma unroll
        for (int ks = 0; ks < 4; ks++) {
            uint32_t a[4][4];
            #pragma unroll
            for (int mf = 0; mf < 4; mf++) {
                int row = wm * 64 + mf * 16 + arow_l;
                int jj  = (ks * 2 + adj) ^ (row & 7);
                LDSM4(a[mf], sa + row * 128 + (jj << 4));
            }
            #pragma unroll
            for (int nfp = 0; nfp < 2; nfp++) {
                int row = wn * 32 + nfp * 16 + brow_l;
                int jj  = (ks * 2 + bdj) ^ (row & 7);
                uint32_t b[4];
                LDSM4(b, sb + row * 128 + (jj << 4));
                #pragma unroll
                for (int mf = 0; mf < 4; mf++)
                    mma_f16(acc[mf][2 * nfp], a[mf], b[0], b[1]);
                #pragma unroll
                for (int mf = 0; mf < 4; mf++)
                    mma_f16(acc[mf][2 * nfp + 1], a[mf], b[2], b[3]);
            }
        }
    }

    #pragma unroll
    for (int mf = 0; mf < 4; mf++) {
        int r = bm * BM + wm * 64 + mf * 16 + (lane >> 2);
        #pragma unroll
        for (int nf = 0; nf < 4; nf++) {
            int cc = bn * BN + wn * 32 + nf * 8 + (lane & 3) * 2;
            stg_cs_f2(&C[(size_t)r       * N + cc], acc[mf][nf][0], acc[mf][nf][1]);
            stg_cs_f2(&C[(size_t)(r + 8) * N + cc], acc[mf][nf][2], acc[mf][nf][3]);
        }
    }
}

// ---------------- CW block GEMM (R15 winner + packed summaries) ----------------
// CTA 64x128, 256 threads, warp tile 32x32 (2x4 warps), BK=64,
// 3-stage cp.async (24 KB/stage, 72 KB) -> 3 CTAs/SM.
// Epilogue: minGRU c,w; fp32 smem staging; packed fp16 (c,w) coalesced stores;
// per-chunk packed float2 summaries (2 chunks x 64 channels per CTA).

#define BM2 64
#define BN2 128
#define A2_BYTES (BM2 * 128)                 // 8 KB
#define B2_BYTES (BN2 * 128)                 // 16 KB
#define STAGE2   (A2_BYTES + B2_BYTES)       // 24 KB
#define CW_SMEM  (GSTAGES * STAGE2)          // 72 KB
#define SUM_STRIDE 68
// staging need: 2 * 64 * 68 * 4 = 34816 <= 73728 OK

__device__ __forceinline__ void load_stage_cw(uint32_t sbase, int stage,
                                              const __half* Ab, const __half* Bb,
                                              int kt, int tid) {
    uint32_t sa = sbase + stage * STAGE2;
    int j = tid & 7;
    int rt = tid >> 3;                     // 0..31
    const __half* Ag = Ab + kt * GBK + j * 8;
    #pragma unroll
    for (int i = 0; i < 2; i++) {
        int r = i * 32 + rt;
        cp_async16(sa + r * 128 + ((j ^ (r & 7)) << 4), Ag + (size_t)r * GK);
    }
    uint32_t sb = sa + A2_BYTES;
    const __half* Bg = Bb + kt * GBK + j * 8;
    #pragma unroll
    for (int i = 0; i < 4; i++) {
        int r = i * 32 + rt;
        cp_async16(sb + r * 128 + ((j ^ (r & 7)) << 4), Bg + (size_t)r * GK);
    }
}

__global__ __launch_bounds__(256, 3)
void gemm_cw(const __half* __restrict__ A, const __half* __restrict__ BT,
             __half2* __restrict__ CW, float2* __restrict__ CsWs) {
    extern __shared__ char smc[];
    uint32_t sbase = smem_u32(smc);

    int tid  = threadIdx.x;
    int lane = tid & 31;
    int wid  = tid >> 5;
    int wm = wid & 1;                 // 2 m-warps (32 rows each)
    int wn = wid >> 1;                // 4 n-warps (32 cols each)
    int bm = blockIdx.x, bn = blockIdx.y;

    const __half* Ab = A  + (size_t)bm * BM2 * GK;
    const __half* Bb = BT + (size_t)bn * BN2 * GK;

    float acc[2][4][4];
    #pragma unroll
    for (int mf = 0; mf < 2; mf++)
        #pragma unroll
        for (int nf = 0; nf < 4; nf++)
            #pragma unroll
            for (int i = 0; i < 4; i++) acc[mf][nf][i] = 0.0f;

    int arow_l = (lane & 7) + ((lane >> 3) & 1) * 8;
    int adj    = (lane >> 4) & 1;
    int brow_l = (lane & 7) + ((lane >> 4) & 1) * 8;
    int bdj    = (lane >> 3) & 1;

    #pragma unroll
    for (int s = 0; s < GSTAGES - 1; s++) {
        load_stage_cw(sbase, s, Ab, Bb, s, tid);
        CP_COMMIT();
    }

    for (int kt = 0; kt < NKT; kt++) {
        CP_WAIT1();
        __syncthreads();

        if (kt + GSTAGES - 1 < NKT)
            load_stage_cw(sbase, (kt + GSTAGES - 1) % GSTAGES, Ab, Bb,
                          kt + GSTAGES - 1, tid);
        CP_COMMIT();

        uint32_t sa = sbase + (kt % GSTAGES) * STAGE2;
        uint32_t sb = sa + A2_BYTES;

        #pragma unroll
        for (int ks = 0; ks < 4; ks++) {
            uint32_t a[2][4];
            #pragma unroll
            for (int mf = 0; mf < 2; mf++) {
                int row = wm * 32 + mf * 16 + arow_l;
                int jj  = (ks * 2 + adj) ^ (row & 7);
                LDSM4(a[mf], sa + row * 128 + (jj << 4));
            }
            #pragma unroll
            for (int nfp = 0; nfp < 2; nfp++) {
                int row = wn * 32 + nfp * 16 + brow_l;
                int jj  = (ks * 2 + bdj) ^ (row & 7);
                uint32_t b[4];
                LDSM4(b, sb + row * 128 + (jj << 4));
                #pragma unroll
                for (int mf = 0; mf < 2; mf++)
                    mma_f16(acc[mf][2 * nfp], a[mf], b[0], b[1]);
                #pragma unroll
                for (int mf = 0; mf < 2; mf++)
                    mma_f16(acc[mf][2 * nfp + 1], a[mf], b[2], b[3]);
            }
        }
    }

    // epilogue: minGRU transform -> fp32 smem staging -> packed fp16 stores
    CP_WAIT0();
    __syncthreads();
    float* sc = (float*)smc;                       // [64][SUM_STRIDE]
    float* sw = sc + BM2 * SUM_STRIDE;

    #pragma unroll
    for (int mf = 0; mf < 2; mf++) {
        int rl = wm * 32 + mf * 16 + (lane >> 2);       // local row 0..63
        #pragma unroll
        for (int nf = 0; nf < 4; nf++) {
            int chl = wn * 16 + nf * 4 + (lane & 3);    // local channel 0..63
            #pragma unroll
            for (int half = 0; half < 2; half++) {
                float hid = acc[mf][nf][2 * half];
                float gat = acc[mf][nf][2 * half + 1];
                float z   = 1.0f / (1.0f + __expf(-gat));
                float ccf = 1.0f / (1.0f + __expf(gat));
                float g   = (hid >= 0.0f) ? (hid + 0.5f)
                                          : (1.0f / (1.0f + __expf(-hid)));
                int rloc  = rl + 8 * half;
                sc[rloc * SUM_STRIDE + chl] = ccf;
                sw[rloc * SUM_STRIDE + chl] = z * g;
            }
        }
    }
    __syncthreads();

    // packed fp16 coalesced stores: 64 rows x 64 half2 = 4096; 256 threads x 16
    #pragma unroll
    for (int i = 0; i < 16; i++) {
        int idx = tid + i * 256;
        int row = idx >> 6;                  // 0..63
        int ch  = idx & 63;
        size_t p = (size_t)(bm * BM2 + row) * DIM + bn * 64 + ch;
        CW[p] = __floats2half2_rn(sc[row * SUM_STRIDE + ch],
                                  sw[row * SUM_STRIDE + ch]);
    }

    // per-chunk packed summaries (fp32): 2 chunks x 64 channels (threads 0..127)
    if (tid < 2 * 64) {
        int cl  = tid >> 6;
        int chl = tid & 63;
        float Cp = 1.0f, Wp = 0.0f;
        #pragma unroll 8
        for (int j = 0; j < CHUNK; j++) {
            float cc = sc[(cl * CHUNK + j) * SUM_STRIDE + chl];
            float ww = sw[(cl * CHUNK + j) * SUM_STRIDE + chl];
            Wp = fmaf(cc, Wp, ww);
            Cp *= cc;
        }
        int chunk_g = bm * 2 + cl;
        CsWs[chunk_g * DIM + bn * 64 + chl] = make_float2(Cp, Wp);
    }
}

// ---------------- host launch ----------------

extern "C" void kernel_launch(void* const* d_in, const int* in_sizes, int n_in,
                              void* d_out, int out_size) {
    const int*   ids         = (const int*)  d_in[0];
    const float* emb         = (const float*)d_in[1];
    const float* w_hg        = (const float*)d_in[2];
    const float* norm_scales = (const float*)d_in[3];
    const float* final_scale = (const float*)d_in[4];
    const float* readout     = (const float*)d_in[5];
    float* out = (float*)d_out;

    float *x;
    float2 *CsWs;
    __half2 *cw;
    __half *xn, *roT, *whgT;
    cudaGetSymbolAddress((void**)&x,    g_x);
    cudaGetSymbolAddress((void**)&xn,   g_xn);
    cudaGetSymbolAddress((void**)&cw,   g_cw);
    cudaGetSymbolAddress((void**)&CsWs, g_CsWs);
    cudaGetSymbolAddress((void**)&roT,  g_roT);
    cudaGetSymbolAddress((void**)&whgT, g_whgT);

    cudaFuncSetAttribute(gemm_ro, cudaFuncAttributeMaxDynamicSharedMemorySize, GEMM_SMEM);
    cudaFuncSetAttribute(gemm_cw, cudaFuncAttributeMaxDynamicSharedMemorySize, CW_SMEM);
    cudaFuncSetAttribute(scan3_norm3<false>, cudaFuncAttributeMaxDynamicSharedMemorySize,
                         CHUNK * DIM * (int)sizeof(float));
    cudaFuncSetAttribute(scan3_norm3<true>, cudaFuncAttributeMaxDynamicSharedMemorySize,
                         CHUNK * DIM * (int)sizeof(float));

    // weight prep (once per replay)
    transpose_h<<<dim3(VOCAB / 32, DIM / 32), dim3(32, 8)>>>(readout, roT, DIM, VOCAB);
    transpose_h_ilv<<<dim3(2 * DIM / 32, DIM / 32, NBLK), dim3(32, 8)>>>(w_hg, whgT, DIM, 2 * DIM);

    embed_norm<<<SEQ, 128>>>(ids, emb, norm_scales, x, xn);

    for (int i = 0; i < NBLK; i++) {
        gemm_cw<<<dim3(SEQ / BM2, 2 * DIM / BN2), 256, CW_SMEM>>>(
            xn, whgT + (size_t)i * 2 * DIM * DIM, cw, CsWs);
        const float* sc = (i + 1 < NBLK) ? (norm_scales + (i + 1) * DIM) : final_scale;
        if (i + 1 < NBLK)
            scan3_norm3<false><<<NCHUNK, DIM, CHUNK * DIM * sizeof(float)>>>(cw, CsWs, sc, x, xn);
        else
            scan3_norm3<true><<<NCHUNK, DIM, CHUNK * DIM * sizeof(float)>>>(cw, CsWs, sc, x, xn);
    }

    gemm_ro<<<dim3(SEQ / BM, VOCAB / BN), 256, GEMM_SMEM>>>(xn, roT, out, VOCAB);

    (void)in_sizes; (void)n_in; (void)out_size;
}

// round 17
// speedup vs baseline: 1.0067x; 1.0067x over previous
#include <cuda_runtime.h>
#include <cuda_fp16.h>
#include <cstdint>

#define SEQ   4096
#define DIM   512
#define VOCAB 32000
#define NBLK  4

#define NCHUNK 128
#define CHUNK  (SEQ / NCHUNK)   // 32

// ---------------- scratch (no allocations allowed) ----------------
__device__ float   g_x [SEQ * DIM];
__device__ __half  g_xn[SEQ * DIM];                 // fp16 rmsnorm output (GEMM A)
__device__ __half2 g_cw[SEQ * DIM];                 // packed (c, w) per element
__device__ float2  g_CsWs[NCHUNK * DIM];            // packed per-chunk (C, W) summaries
__device__ __half  g_roT [VOCAB * DIM];             // readout^T  [32000, 512] fp16
__device__ __half  g_whgT[NBLK * 2 * DIM * DIM];    // w_hg^T, column-interleaved, fp16

// ---------------- helpers ----------------
__device__ __forceinline__ uint32_t smem_u32(const void* p) {
    return (uint32_t)__cvta_generic_to_shared(p);
}
__device__ __forceinline__ void cp_async16(uint32_t saddr, const void* gmem) {
    asm volatile("cp.async.cg.shared.global [%0], [%1], 16;\n" :: "r"(saddr), "l"(gmem));
}
#define CP_COMMIT() asm volatile("cp.async.commit_group;\n" ::: "memory")
#define CP_WAIT1()  asm volatile("cp.async.wait_group 1;\n" ::: "memory")
#define CP_WAIT0()  asm volatile("cp.async.wait_group 0;\n" ::: "memory")

#define LDSM4(r, addr) \
    asm volatile("ldmatrix.sync.aligned.m8n8.x4.shared.b16 {%0,%1,%2,%3}, [%4];" \
        : "=r"((r)[0]), "=r"((r)[1]), "=r"((r)[2]), "=r"((r)[3]) : "r"(addr))

__device__ __forceinline__ void mma_f16(float* c, const uint32_t* a,
                                        uint32_t b0, uint32_t b1) {
    asm volatile(
        "mma.sync.aligned.m16n8k16.row.col.f32.f16.f16.f32 "
        "{%0,%1,%2,%3}, {%4,%5,%6,%7}, {%8,%9}, {%0,%1,%2,%3};"
        : "+f"(c[0]), "+f"(c[1]), "+f"(c[2]), "+f"(c[3])
        : "r"(a[0]), "r"(a[1]), "r"(a[2]), "r"(a[3]), "r"(b0), "r"(b1));
}

// streaming (evict-first) store: output logits are never reread -> keep B in L2
__device__ __forceinline__ void stg_cs_f2(float* p, float a, float b) {
    asm volatile("st.global.cs.v2.f32 [%0], {%1, %2};" :: "l"(p), "f"(a), "f"(b) : "memory");
}

// ---------------- elementwise / prep kernels ----------------

// readout: src [K, N] f32 -> dst [N, K] fp16
__global__ void transpose_h(const float* __restrict__ src, __half* __restrict__ dst,
                            int K, int N) {
    __shared__ float t[32][33];
    int n0 = blockIdx.x * 32, k0 = blockIdx.y * 32;
    int tx = threadIdx.x, ty = threadIdx.y;                 // 32 x 8
    #pragma unroll
    for (int i = 0; i < 32; i += 8)
        t[ty + i][tx] = src[(size_t)(k0 + ty + i) * N + n0 + tx];
    __syncthreads();
    #pragma unroll
    for (int i = 0; i < 32; i += 8)
        dst[(size_t)(n0 + ty + i) * K + k0 + tx] = __float2half_rn(t[tx][ty + i]);
}

// w_hg: src [K, 2D] f32 -> dst [2D, K] fp16, column-interleaved:
//   hidden ch n -> row 2n, gate ch n -> row 2n+1
__global__ void transpose_h_ilv(const float* __restrict__ src0, __half* __restrict__ dst0,
                                int K, int N) {
    const float* src = src0 + (size_t)blockIdx.z * K * N;
    __half* dst = dst0 + (size_t)blockIdx.z * N * K;
    __shared__ float t[32][33];
    int n0 = blockIdx.x * 32, k0 = blockIdx.y * 32;
    int tx = threadIdx.x, ty = threadIdx.y;
    #pragma unroll
    for (int i = 0; i < 32; i += 8)
        t[ty + i][tx] = src[(size_t)(k0 + ty + i) * N + n0 + tx];
    __syncthreads();
    #pragma unroll
    for (int i = 0; i < 32; i += 8) {
        int n = n0 + ty + i;
        int np = (n < DIM) ? (2 * n) : (2 * (n - DIM) + 1);
        dst[(size_t)np * K + k0 + tx] = __float2half_rn(t[tx][ty + i]);
    }
}

// fused embed gather + rmsnorm: x = emb[ids], xn = rmsnorm(x)*scale (fp16)
__global__ void embed_norm(const int* __restrict__ ids,
                           const float* __restrict__ emb,
                           const float* __restrict__ scale,
                           float* __restrict__ x, __half* __restrict__ xn) {
    int t = blockIdx.x;
    int tid = threadIdx.x;                                // 128 threads, 4 f32 each
    float4 v = ((const float4*)(emb + (size_t)ids[t] * DIM))[tid];
    ((float4*)(x + (size_t)t * DIM))[tid] = v;
    float ss = v.x * v.x + v.y * v.y + v.z * v.z + v.w * v.w;
    #pragma unroll
    for (int o = 16; o; o >>= 1) ss += __shfl_xor_sync(0xffffffffu, ss, o);
    __shared__ float sred[4];
    if ((tid & 31) == 0) sred[tid >> 5] = ss;
    __syncthreads();
    ss = sred[0] + sred[1] + sred[2] + sred[3];
    float r = rsqrtf(ss * (1.0f / DIM) + 1e-6f);
    float4 s = ((const float4*)scale)[tid];
    __half2 h0 = __floats2half2_rn(v.x * r * s.x, v.y * r * s.y);
    __half2 h1 = __floats2half2_rn(v.z * r * s.z, v.w * r * s.w);
    ((__half2*)(xn + (size_t)t * DIM))[2 * tid]     = h0;
    ((__half2*)(xn + (size_t)t * DIM))[2 * tid + 1] = h1;
}

// ---------------- scan kernel ----------------
// fused: per-block carry from packed chunk summaries, apply scan + residual,
// stage tile in smem (ONE barrier), then per-timestep rmsnorm -> fp16 xn.
// LAST: skip the (dead) x writeback on the final layer.
template<bool LAST>
__global__ void scan3_norm3(const __half2* __restrict__ cw,
                            const float2* __restrict__ CsWs,
                            const float* __restrict__ scale,
                            float* __restrict__ x, __half* __restrict__ xn) {
    extern __shared__ float sx[];                         // [CHUNK][DIM]
    int d = threadIdx.x;                                  // 512
    int b = blockIdx.x;

    // carry: prefix of chunk summaries 0..b-1 (fp32-accurate)
    float h = 0.0f;
    for (int j = 0; j < b; j++) {
        float2 s = CsWs[j * DIM + d];
        h = fmaf(s.x, h, s.y);
    }

    size_t base = (size_t)b * CHUNK * DIM + d;
    #pragma unroll 4
    for (int j = 0; j < CHUNK; j++) {
        size_t p = base + (size_t)j * DIM;
        float2 v2 = __half22float2(cw[p]);
        h = fmaf(v2.x, h, v2.y);
        float xv = x[p] + h;
        if (!LAST) x[p] = xv;
        sx[j * DIM + d] = xv;
    }
    __syncthreads();

    int lane = d & 31, wid = d >> 5;                      // 16 warps
    #pragma unroll
    for (int ts = wid; ts < CHUNK; ts += 16) {
        const float4* row = (const float4*)(sx + ts * DIM);
        float4 v[4];
        float ss = 0.0f;
        #pragma unroll
        for (int i = 0; i < 4; i++) {
            v[i] = row[lane * 4 + i];
            ss += v[i].x * v[i].x + v[i].y * v[i].y + v[i].z * v[i].z + v[i].w * v[i].w;
        }
        #pragma unroll
        for (int o = 16; o; o >>= 1) ss += __shfl_xor_sync(0xffffffffu, ss, o);
        float r = rsqrtf(ss * (1.0f / DIM) + 1e-6f);
        __half2* dst = (__half2*)(xn + ((size_t)(b * CHUNK + ts)) * DIM + lane * 16);
        #pragma unroll
        for (int i = 0; i < 4; i++) {
            float4 s = ((const float4*)scale)[lane * 4 + i];
            dst[2 * i]     = __floats2half2_rn(v[i].x * r * s.x, v[i].y * r * s.y);
            dst[2 * i + 1] = __floats2half2_rn(v[i].z * r * s.z, v[i].w * r * s.w);
        }
    }
}

// ---------------- readout GEMM (A-fragment software pipelining) ----------------
// CTA 128x128, 256 threads, warp tile 64x32 (2x4 warps), BK=64,
// 3-stage cp.async (96 KB) -> 2 CTAs/SM.  f32 C via streaming stores.
// A fragments double-buffered across ks steps: LDSM for ks+1 issued before
// the HMMAs of ks, hiding the 29-cyc smem latency in the dependency chain.

#define GK  512
#define GBK 64
#define NKT (GK / GBK)                     // 8
#define BM  128
#define BN  128
#define GSTAGES 3
#define A_BYTES (BM * 128)                 // 16 KB
#define B_BYTES (BN * 128)                 // 16 KB
#define STAGE_BYTES (A_BYTES + B_BYTES)    // 32 KB
#define GEMM_SMEM (GSTAGES * STAGE_BYTES)  // 96 KB

__device__ __forceinline__ void load_stage_g(uint32_t sbase, int stage,
                                             const __half* Ab, const __half* Bb,
                                             int kt, int tid) {
    uint32_t sa = sbase + stage * STAGE_BYTES;
    int j = tid & 7;
    int rt = tid >> 3;                     // 0..31
    const __half* Ag = Ab + kt * GBK + j * 8;
    #pragma unroll
    for (int i = 0; i < 4; i++) {
        int r = i * 32 + rt;
        cp_async16(sa + r * 128 + ((j ^ (r & 7)) << 4), Ag + (size_t)r * GK);
    }
    uint32_t sb = sa + A_BYTES;
    const __half* Bg = Bb + kt * GBK + j * 8;
    #pragma unroll
    for (int i = 0; i < 4; i++) {
        int r = i * 32 + rt;
        cp_async16(sb + r * 128 + ((j ^ (r & 7)) << 4), Bg + (size_t)r * GK);
    }
}

__global__ __launch_bounds__(256, 2)
void gemm_ro(const __half* __restrict__ A, const __half* __restrict__ BT,
             float* __restrict__ C, int N) {
    extern __shared__ char smc[];
    uint32_t sbase = smem_u32(smc);

    int tid  = threadIdx.x;
    int lane = tid & 31;
    int wid  = tid >> 5;
    int wm = wid & 1;
    int wn = wid >> 1;
    int bm = blockIdx.x, bn = blockIdx.y;

    const __half* Ab = A  + (size_t)bm * BM * GK;
    const __half* Bb = BT + (size_t)bn * BN * GK;

    float acc[4][4][4];
    #pragma unroll
    for (int mf = 0; mf < 4; mf++)
        #pragma unroll
        for (int nf = 0; nf < 4; nf++)
            #pragma unroll
            for (int i = 0; i < 4; i++) acc[mf][nf][i] = 0.0f;

    int arow_l = (lane & 7) + ((lane >> 3) & 1) * 8;
    int adj    = (lane >> 4) & 1;
    int brow_l = (lane & 7) + ((lane >> 4) & 1) * 8;
    int bdj    = (lane >> 3) & 1;

    #pragma unroll
    for (int s = 0; s < GSTAGES - 1; s++) {
        load_stage_g(sbase, s, Ab, Bb, s, tid);
        CP_COMMIT();
    }

    for (int kt = 0; kt < NKT; kt++) {
        CP_WAIT1();
        __syncthreads();

        if (kt + GSTAGES - 1 < NKT)
            load_stage_g(sbase, (kt + GSTAGES - 1) % GSTAGES, Ab, Bb,
                         kt + GSTAGES - 1, tid);
        CP_COMMIT();

        uint32_t sa = sbase + (kt % GSTAGES) * STAGE_BYTES;
        uint32_t sb = sa + A_BYTES;

        // A-fragment double buffer across the 4 ks steps
        uint32_t a[2][4][4];
        #pragma unroll
        for (int mf = 0; mf < 4; mf++) {
            int row = wm * 64 + mf * 16 + arow_l;
            int jj  = adj ^ (row & 7);                    // ks = 0
            LDSM4(a[0][mf], sa + row * 128 + (jj << 4));
        }

        #pragma unroll
        for (int ks = 0; ks < 4; ks++) {
            int cur = ks & 1, nxt = cur ^ 1;
            if (ks < 3) {
                #pragma unroll
                for (int mf = 0; mf < 4; mf++) {
                    int row = wm * 64 + mf * 16 + arow_l;
                    int jj  = ((ks + 1) * 2 + adj) ^ (row & 7);
                    LDSM4(a[nxt][mf], sa + row * 128 + (jj << 4));
                }
            }
            #pragma unroll
            for (int nfp = 0; nfp < 2; nfp++) {
                int row = wn * 32 + nfp * 16 + brow_l;
                int jj  = (ks * 2 + bdj) ^ (row & 7);
                uint32_t b[4];
                LDSM4(b, sb + row * 128 + (jj << 4));
                #pragma unroll
                for (int mf = 0; mf < 4; mf++)
                    mma_f16(acc[mf][2 * nfp], a[cur][mf], b[0], b[1]);
                #pragma unroll
                for (int mf = 0; mf < 4; mf++)
                    mma_f16(acc[mf][2 * nfp + 1], a[cur][mf], b[2], b[3]);
            }
        }
    }

    #pragma unroll
    for (int mf = 0; mf < 4; mf++) {
        int r = bm * BM + wm * 64 + mf * 16 + (lane >> 2);
        #pragma unroll
        for (int nf = 0; nf < 4; nf++) {
            int cc = bn * BN + wn * 32 + nf * 8 + (lane & 3) * 2;
            stg_cs_f2(&C[(size_t)r       * N + cc], acc[mf][nf][0], acc[mf][nf][1]);
            stg_cs_f2(&C[(size_t)(r + 8) * N + cc], acc[mf][nf][2], acc[mf][nf][3]);
        }
    }
}

// ---------------- CW block GEMM (unchanged R15/R16 winner) ----------------
// CTA 64x128, 256 threads, warp tile 32x32 (2x4 warps), BK=64,
// 3-stage cp.async (24 KB/stage, 72 KB) -> 3 CTAs/SM.
// Epilogue: minGRU c,w; fp32 smem staging; packed fp16 (c,w) coalesced stores;
// per-chunk packed float2 summaries (2 chunks x 64 channels per CTA).

#define BM2 64
#define BN2 128
#define A2_BYTES (BM2 * 128)                 // 8 KB
#define B2_BYTES (BN2 * 128)                 // 16 KB
#define STAGE2   (A2_BYTES + B2_BYTES)       // 24 KB
#define CW_SMEM  (GSTAGES * STAGE2)          // 72 KB
#define SUM_STRIDE 68
// staging need: 2 * 64 * 68 * 4 = 34816 <= 73728 OK

__device__ __forceinline__ void load_stage_cw(uint32_t sbase, int stage,
                                              const __half* Ab, const __half* Bb,
                                              int kt, int tid) {
    uint32_t sa = sbase + stage * STAGE2;
    int j = tid & 7;
    int rt = tid >> 3;                     // 0..31
    const __half* Ag = Ab + kt * GBK + j * 8;
    #pragma unroll
    for (int i = 0; i < 2; i++) {
        int r = i * 32 + rt;
        cp_async16(sa + r * 128 + ((j ^ (r & 7)) << 4), Ag + (size_t)r * GK);
    }
    uint32_t sb = sa + A2_BYTES;
    const __half* Bg = Bb + kt * GBK + j * 8;
    #pragma unroll
    for (int i = 0; i < 4; i++) {
        int r = i * 32 + rt;
        cp_async16(sb + r * 128 + ((j ^ (r & 7)) << 4), Bg + (size_t)r * GK);
    }
}

__global__ __launch_bounds__(256, 3)
void gemm_cw(const __half* __restrict__ A, const __half* __restrict__ BT,
             __half2* __restrict__ CW, float2* __restrict__ CsWs) {
    extern __shared__ char smc[];
    uint32_t sbase = smem_u32(smc);

    int tid  = threadIdx.x;
    int lane = tid & 31;
    int wid  = tid >> 5;
    int wm = wid & 1;                 // 2 m-warps (32 rows each)
    int wn = wid >> 1;                // 4 n-warps (32 cols each)
    int bm = blockIdx.x, bn = blockIdx.y;

    const __half* Ab = A  + (size_t)bm * BM2 * GK;
    const __half* Bb = BT + (size_t)bn * BN2 * GK;

    float acc[2][4][4];
    #pragma unroll
    for (int mf = 0; mf < 2; mf++)
        #pragma unroll
        for (int nf = 0; nf < 4; nf++)
            #pragma unroll
            for (int i = 0; i < 4; i++) acc[mf][nf][i] = 0.0f;

    int arow_l = (lane & 7) + ((lane >> 3) & 1) * 8;
    int adj    = (lane >> 4) & 1;
    int brow_l = (lane & 7) + ((lane >> 4) & 1) * 8;
    int bdj    = (lane >> 3) & 1;

    #pragma unroll
    for (int s = 0; s < GSTAGES - 1; s++) {
        load_stage_cw(sbase, s, Ab, Bb, s, tid);
        CP_COMMIT();
    }

    for (int kt = 0; kt < NKT; kt++) {
        CP_WAIT1();
        __syncthreads();

        if (kt + GSTAGES - 1 < NKT)
            load_stage_cw(sbase, (kt + GSTAGES - 1) % GSTAGES, Ab, Bb,
                          kt + GSTAGES - 1, tid);
        CP_COMMIT();

        uint32_t sa = sbase + (kt % GSTAGES) * STAGE2;
        uint32_t sb = sa + A2_BYTES;

        #pragma unroll
        for (int ks = 0; ks < 4; ks++) {
            uint32_t a[2][4];
            #pragma unroll
            for (int mf = 0; mf < 2; mf++) {
                int row = wm * 32 + mf * 16 + arow_l;
                int jj  = (ks * 2 + adj) ^ (row & 7);
                LDSM4(a[mf], sa + row * 128 + (jj << 4));
            }
            #pragma unroll
            for (int nfp = 0; nfp < 2; nfp++) {
                int row = wn * 32 + nfp * 16 + brow_l;
                int jj  = (ks * 2 + bdj) ^ (row & 7);
                uint32_t b[4];
                LDSM4(b, sb + row * 128 + (jj << 4));
                #pragma unroll
                for (int mf = 0; mf < 2; mf++)
                    mma_f16(acc[mf][2 * nfp], a[mf], b[0], b[1]);
                #pragma unroll
                for (int mf = 0; mf < 2; mf++)
                    mma_f16(acc[mf][2 * nfp + 1], a[mf], b[2], b[3]);
            }
        }
    }

    // epilogue: minGRU transform -> fp32 smem staging -> packed fp16 stores
    CP_WAIT0();
    __syncthreads();
    float* sc = (float*)smc;                       // [64][SUM_STRIDE]
    float* sw = sc + BM2 * SUM_STRIDE;

    #pragma unroll
    for (int mf = 0; mf < 2; mf++) {
        int rl = wm * 32 + mf * 16 + (lane >> 2);       // local row 0..63
        #pragma unroll
        for (int nf = 0; nf < 4; nf++) {
            int chl = wn * 16 + nf * 4 + (lane & 3);    // local channel 0..63
            #pragma unroll
            for (int half = 0; half < 2; half++) {
                float hid = acc[mf][nf][2 * half];
                float gat = acc[mf][nf][2 * half + 1];
                float z   = 1.0f / (1.0f + __expf(-gat));
                float ccf = 1.0f / (1.0f + __expf(gat));
                float g   = (hid >= 0.0f) ? (hid + 0.5f)
                                          : (1.0f / (1.0f + __expf(-hid)));
                int rloc  = rl + 8 * half;
                sc[rloc * SUM_STRIDE + chl] = ccf;
                sw[rloc * SUM_STRIDE + chl] = z * g;
            }
        }
    }
    __syncthreads();

    // packed fp16 coalesced stores: 64 rows x 64 half2 = 4096; 256 threads x 16
    #pragma unroll
    for (int i = 0; i < 16; i++) {
        int idx = tid + i * 256;
        int row = idx >> 6;                  // 0..63
        int ch  = idx & 63;
        size_t p = (size_t)(bm * BM2 + row) * DIM + bn * 64 + ch;
        CW[p] = __floats2half2_rn(sc[row * SUM_STRIDE + ch],
                                  sw[row * SUM_STRIDE + ch]);
    }

    // per-chunk packed summaries (fp32): 2 chunks x 64 channels (threads 0..127)
    if (tid < 2 * 64) {
        int cl  = tid >> 6;
        int chl = tid & 63;
        float Cp = 1.0f, Wp = 0.0f;
        #pragma unroll 8
        for (int j = 0; j < CHUNK; j++) {
            float cc = sc[(cl * CHUNK + j) * SUM_STRIDE + chl];
            float ww = sw[(cl * CHUNK + j) * SUM_STRIDE + chl];
            Wp = fmaf(cc, Wp, ww);
            Cp *= cc;
        }
        int chunk_g = bm * 2 + cl;
        CsWs[chunk_g * DIM + bn * 64 + chl] = make_float2(Cp, Wp);
    }
}

// ---------------- host launch ----------------

extern "C" void kernel_launch(void* const* d_in, const int* in_sizes, int n_in,
                              void* d_out, int out_size) {
    const int*   ids         = (const int*)  d_in[0];
    const float* emb         = (const float*)d_in[1];
    const float* w_hg        = (const float*)d_in[2];
    const float* norm_scales = (const float*)d_in[3];
    const float* final_scale = (const float*)d_in[4];
    const float* readout     = (const float*)d_in[5];
    float* out = (float*)d_out;

    float *x;
    float2 *CsWs;
    __half2 *cw;
    __half *xn, *roT, *whgT;
    cudaGetSymbolAddress((void**)&x,    g_x);
    cudaGetSymbolAddress((void**)&xn,   g_xn);
    cudaGetSymbolAddress((void**)&cw,   g_cw);
    cudaGetSymbolAddress((void**)&CsWs, g_CsWs);
    cudaGetSymbolAddress((void**)&roT,  g_roT);
    cudaGetSymbolAddress((void**)&whgT, g_whgT);

    cudaFuncSetAttribute(gemm_ro, cudaFuncAttributeMaxDynamicSharedMemorySize, GEMM_SMEM);
    cudaFuncSetAttribute(gemm_cw, cudaFuncAttributeMaxDynamicSharedMemorySize, CW_SMEM);
    cudaFuncSetAttribute(scan3_norm3<false>, cudaFuncAttributeMaxDynamicSharedMemorySize,
                         CHUNK * DIM * (int)sizeof(float));
    cudaFuncSetAttribute(scan3_norm3<true>, cudaFuncAttributeMaxDynamicSharedMemorySize,
                         CHUNK * DIM * (int)sizeof(float));

    // weight prep (once per replay)
    transpose_h<<<dim3(VOCAB / 32, DIM / 32), dim3(32, 8)>>>(readout, roT, DIM, VOCAB);
    transpose_h_ilv<<<dim3(2 * DIM / 32, DIM / 32, NBLK), dim3(32, 8)>>>(w_hg, whgT, DIM, 2 * DIM);

    embed_norm<<<SEQ, 128>>>(ids, emb, norm_scales, x, xn);

    for (int i = 0; i < NBLK; i++) {
        gemm_cw<<<dim3(SEQ / BM2, 2 * DIM / BN2), 256, CW_SMEM>>>(
            xn, whgT + (size_t)i * 2 * DIM * DIM, cw, CsWs);
        const float* sc = (i + 1 < NBLK) ? (norm_scales + (i + 1) * DIM) : final_scale;
        if (i + 1 < NBLK)
            scan3_norm3<false><<<NCHUNK, DIM, CHUNK * DIM * sizeof(float)>>>(cw, CsWs, sc, x, xn);
        else
            scan3_norm3<true><<<NCHUNK, DIM, CHUNK * DIM * sizeof(float)>>>(cw, CsWs, sc, x, xn);
    }

    gemm_ro<<<dim3(SEQ / BM, VOCAB / BN), 256, GEMM_SMEM>>>(xn, roT, out, VOCAB);

    (void)in_sizes; (void)n_in; (void)out_size;
}